// round 1
// baseline (speedup 1.0000x reference)
#include <cuda_runtime.h>

// Problem geometry (fixed)
#define Bb    4
#define Nn    512
#define Hh    12
#define Dh    64
#define HIDD  768
#define Ee    65536
#define NSEG  2048          // Bb*Nn segments
#define NCHUNK 256
#define CHUNK  256          // NCHUNK*CHUNK == Ee
#define CAP    512          // max edges per segment handled (Poisson(32), max ~70)

// ---------------- device scratch (static; no allocations allowed) ----------------
__device__ float g_Q[NSEG * HIDD];
__device__ float g_K[NSEG * HIDD];
__device__ float g_V[NSEG * HIDD];
__device__ float g_logits[Ee * Hh];
__device__ int   g_hist[NCHUNK * NSEG];
__device__ int   g_base[NCHUNK * NSEG];
__device__ int   g_cnt[NSEG];
__device__ int   g_start[NSEG + 1];
__device__ int   g_sorted[Ee];

// ---------------- 1) QKV projection GEMM: y = x @ W^T + b ----------------
// 128x128 tile, BK=8, 256 threads, 8x8 microtile. blockIdx.z selects Q/K/V.
__global__ __launch_bounds__(256, 2) void qkv_gemm(
    const float* __restrict__ x,
    const float* __restrict__ Wq, const float* __restrict__ Wk, const float* __restrict__ Wv,
    const float* __restrict__ bq, const float* __restrict__ bk, const float* __restrict__ bv)
{
    const float* W; const float* bias; float* out;
    if (blockIdx.z == 0)      { W = Wq; bias = bq; out = g_Q; }
    else if (blockIdx.z == 1) { W = Wk; bias = bk; out = g_K; }
    else                      { W = Wv; bias = bv; out = g_V; }

    __shared__ float As[8][128];
    __shared__ float Bs[8][128];

    const int t  = threadIdx.x;
    const int i0 = blockIdx.y * 128;
    const int j0 = blockIdx.x * 128;
    const int lr = t >> 1;            // 0..127 (row within tile for loading)
    const int q4 = (t & 1) * 4;       // which half of 8 K-values
    const int tx = t & 15;            // 0..15
    const int ty = t >> 4;            // 0..15

    float acc[8][8];
    #pragma unroll
    for (int u = 0; u < 8; u++)
        #pragma unroll
        for (int v = 0; v < 8; v++) acc[u][v] = 0.f;

    for (int k0 = 0; k0 < HIDD; k0 += 8) {
        float4 av = *(const float4*)&x[(i0 + lr) * HIDD + k0 + q4];
        float4 wv = *(const float4*)&W[(j0 + lr) * HIDD + k0 + q4];
        As[q4 + 0][lr] = av.x; As[q4 + 1][lr] = av.y; As[q4 + 2][lr] = av.z; As[q4 + 3][lr] = av.w;
        Bs[q4 + 0][lr] = wv.x; Bs[q4 + 1][lr] = wv.y; Bs[q4 + 2][lr] = wv.z; Bs[q4 + 3][lr] = wv.w;
        __syncthreads();

        #pragma unroll
        for (int kk = 0; kk < 8; kk++) {
            float4 a0 = *(const float4*)&As[kk][ty * 4];
            float4 a1 = *(const float4*)&As[kk][64 + ty * 4];
            float4 b0 = *(const float4*)&Bs[kk][tx * 4];
            float4 b1 = *(const float4*)&Bs[kk][64 + tx * 4];
            float ar[8] = {a0.x, a0.y, a0.z, a0.w, a1.x, a1.y, a1.z, a1.w};
            float br[8] = {b0.x, b0.y, b0.z, b0.w, b1.x, b1.y, b1.z, b1.w};
            #pragma unroll
            for (int u = 0; u < 8; u++)
                #pragma unroll
                for (int v = 0; v < 8; v++) acc[u][v] += ar[u] * br[v];
        }
        __syncthreads();
    }

    #pragma unroll
    for (int u = 0; u < 8; u++) {
        int r = i0 + ((u < 4) ? (ty * 4 + u) : (64 + ty * 4 + (u - 4)));
        #pragma unroll
        for (int v = 0; v < 8; v++) {
            int c = j0 + ((v < 4) ? (tx * 4 + v) : (64 + tx * 4 + (v - 4)));
            out[r * HIDD + c] = acc[u][v] + bias[c];
        }
    }
}

// ---------------- 2) deterministic counting sort by segment ----------------
__global__ void khist(const int* __restrict__ ei)
{
    __shared__ int cnt[NSEG];
    const int c = blockIdx.x;
    for (int i = threadIdx.x; i < NSEG; i += 256) cnt[i] = 0;
    __syncthreads();
    const int e = c * CHUNK + threadIdx.x;
    const int s = ei[e] * Nn + ei[Ee + e];
    atomicAdd(&cnt[s], 1);
    __syncthreads();
    for (int i = threadIdx.x; i < NSEG; i += 256) g_hist[c * NSEG + i] = cnt[i];
}

__global__ void kcol()
{
    const int s = blockIdx.x * 256 + threadIdx.x;
    int sum = 0;
    for (int c = 0; c < NCHUNK; c++) sum += g_hist[c * NSEG + s];
    g_cnt[s] = sum;
}

__global__ void kscan()
{
    __shared__ int bufA[NSEG];
    __shared__ int bufB[NSEG];
    const int t = threadIdx.x;   // 1024
    for (int i = t; i < NSEG; i += 1024) bufA[i] = g_cnt[i];
    __syncthreads();
    int* src = bufA; int* dst = bufB;
    for (int off = 1; off < NSEG; off <<= 1) {
        for (int i = t; i < NSEG; i += 1024)
            dst[i] = src[i] + ((i >= off) ? src[i - off] : 0);
        __syncthreads();
        int* tmp = src; src = dst; dst = tmp;
    }
    for (int i = t; i < NSEG; i += 1024) g_start[i + 1] = src[i];
    if (t == 0) g_start[0] = 0;
}

__global__ void kbase()
{
    const int s = blockIdx.x * 256 + threadIdx.x;
    int run = g_start[s];
    for (int c = 0; c < NCHUNK; c++) {
        g_base[c * NSEG + s] = run;
        run += g_hist[c * NSEG + s];
    }
}

__global__ void kscatter(const int* __restrict__ ei)
{
    __shared__ int segs[CHUNK];
    const int c = blockIdx.x;
    const int t = threadIdx.x;
    const int e = c * CHUNK + t;
    const int s = ei[e] * Nn + ei[Ee + e];
    segs[t] = s;
    __syncthreads();
    int rank = 0;
    for (int i = 0; i < t; i++) rank += (segs[i] == s);
    g_sorted[g_base[c * NSEG + s] + rank] = e;
}

// ---------------- 3) per-edge relation logits ----------------
// One 64-thread block per edge. Re (64x64) + q-row + k-row in smem.
// Thread tile: 3 heads x 4 k-values; logits[e,h] = sum_k (sum_d q[h,d]*Re[d,k]) * kvec[h,k] / 8
__global__ __launch_bounds__(64) void kedge(const int* __restrict__ ei,
                                            const float* __restrict__ rel)
{
    __shared__ float Re[64 * 64];
    __shared__ float qs[HIDD];
    __shared__ float ks[HIDD];

    const int e = blockIdx.x;
    const int t = threadIdx.x;
    const int b  = ei[e];
    const int hn = ei[Ee + e];
    const int tn = ei[2 * Ee + e];
    const int r  = ei[3 * Ee + e];

    const float4* rp = (const float4*)(rel + (long)r * 4096);
    float4* Rp = (float4*)Re;
    #pragma unroll 4
    for (int i = t; i < 1024; i += 64) Rp[i] = rp[i];

    const float4* qp = (const float4*)(g_Q + (b * Nn + hn) * HIDD);
    const float4* kp = (const float4*)(g_K + (b * Nn + tn) * HIDD);
    float4* qd = (float4*)qs;
    float4* kd = (float4*)ks;
    #pragma unroll
    for (int i = t; i < 192; i += 64) { qd[i] = qp[i]; kd[i] = kp[i]; }
    __syncthreads();

    const int hg = t >> 4;       // 0..3
    const int kq = t & 15;       // 0..15
    const int k0 = kq * 4;

    float acc[3][4];
    #pragma unroll
    for (int j = 0; j < 3; j++)
        #pragma unroll
        for (int v = 0; v < 4; v++) acc[j][v] = 0.f;

    #pragma unroll
    for (int d0 = 0; d0 < 64; d0 += 4) {
        float qa[3][4];
        #pragma unroll
        for (int j = 0; j < 3; j++) {
            float4 qv = *(const float4*)&qs[(hg + 4 * j) * 64 + d0];
            qa[j][0] = qv.x; qa[j][1] = qv.y; qa[j][2] = qv.z; qa[j][3] = qv.w;
        }
        #pragma unroll
        for (int dd = 0; dd < 4; dd++) {
            float4 rv = *(const float4*)&Re[(d0 + dd) * 64 + k0];
            #pragma unroll
            for (int j = 0; j < 3; j++) {
                acc[j][0] += qa[j][dd] * rv.x;
                acc[j][1] += qa[j][dd] * rv.y;
                acc[j][2] += qa[j][dd] * rv.z;
                acc[j][3] += qa[j][dd] * rv.w;
            }
        }
    }

    float part[3];
    #pragma unroll
    for (int j = 0; j < 3; j++) {
        float4 kv = *(const float4*)&ks[(hg + 4 * j) * 64 + k0];
        part[j] = acc[j][0] * kv.x + acc[j][1] * kv.y + acc[j][2] * kv.z + acc[j][3] * kv.w;
    }
    #pragma unroll
    for (int off = 8; off; off >>= 1) {
        #pragma unroll
        for (int j = 0; j < 3; j++)
            part[j] += __shfl_down_sync(0xffffffffu, part[j], off, 16);
    }
    if (kq == 0) {
        #pragma unroll
        for (int j = 0; j < 3; j++)
            g_logits[e * Hh + hg + 4 * j] = part[j] * 0.125f;  // / sqrt(64)
    }
}

// ---------------- 4) per-segment softmax + V aggregation ----------------
__global__ __launch_bounds__(128) void kagg(const int* __restrict__ ei,
                                            float* __restrict__ out)
{
    __shared__ float    exb[CAP * Hh];   // 24 KB
    __shared__ int      voff[CAP];       // 2 KB
    __shared__ unsigned umax[Hh];
    __shared__ float    mx[Hh], dnm[Hh];

    const int s = blockIdx.x;
    const int t = threadIdx.x;
    const int beg = g_start[s];
    int cnt = g_start[s + 1] - beg;
    if (cnt > CAP) cnt = CAP;   // never hit with this data distribution
    float* orow = out + s * HIDD;

    if (cnt == 0) {
        #pragma unroll
        for (int j = 0; j < 6; j++) orow[t + 128 * j] = 0.f;
        return;
    }

    if (t < Hh) umax[t] = 0u;
    __syncthreads();

    for (int i = t; i < cnt; i += 128) {
        int e = g_sorted[beg + i];
        voff[i] = (ei[e] * Nn + ei[2 * Ee + e]) * HIDD;
    }
    for (int j = t; j < cnt * Hh; j += 128) {
        int i = j / Hh;
        int h = j - i * Hh;
        int e = g_sorted[beg + i];
        float l = g_logits[e * Hh + h];
        exb[j] = l;
        unsigned bits = __float_as_uint(l);
        unsigned key  = (bits & 0x80000000u) ? ~bits : (bits | 0x80000000u);
        atomicMax(&umax[h], key);   // max is order-independent -> deterministic
    }
    __syncthreads();

    if (t < Hh) {
        unsigned key  = umax[t];
        unsigned bits = (key & 0x80000000u) ? (key & 0x7fffffffu) : ~key;
        mx[t] = __uint_as_float(bits);
    }
    __syncthreads();

    for (int j = t; j < cnt * Hh; j += 128) {
        int h = j % Hh;
        exb[j] = __expf(exb[j] - mx[h]);
    }
    __syncthreads();

    // deterministic per-head sums: warp w reduces heads 3w..3w+2 with a fixed shuffle tree
    const int w = t >> 5, lane = t & 31;
    #pragma unroll
    for (int jj = 0; jj < 3; jj++) {
        int h = w * 3 + jj;
        float p = 0.f;
        for (int i = lane; i < cnt; i += 32) p += exb[i * Hh + h];
        #pragma unroll
        for (int off = 16; off; off >>= 1) p += __shfl_xor_sync(0xffffffffu, p, off);
        if (lane == 0) dnm[h] = p;
    }
    __syncthreads();

    float rd[6], accr[6];
    int hcol[6];
    #pragma unroll
    for (int j = 0; j < 6; j++) {
        int c = t + 128 * j;
        hcol[j] = c >> 6;
        rd[j] = 1.f / dnm[hcol[j]];
        accr[j] = 0.f;
    }
    for (int i = 0; i < cnt; i++) {
        const float* vrow = g_V + voff[i];
        const float* exr  = &exb[i * Hh];
        #pragma unroll
        for (int j = 0; j < 6; j++) {
            float p = exr[hcol[j]] * rd[j];
            accr[j] += p * vrow[t + 128 * j];
        }
    }
    #pragma unroll
    for (int j = 0; j < 6; j++) orow[t + 128 * j] = accr[j];
}

// ---------------- launch ----------------
extern "C" void kernel_launch(void* const* d_in, const int* in_sizes, int n_in,
                              void* d_out, int out_size)
{
    const float* node_states = (const float*)d_in[0];
    const int*   edge_idx    = (const int*)  d_in[1];
    // d_in[2] = node_type_ids (unused)
    const float* Wq = (const float*)d_in[3];
    const float* bq = (const float*)d_in[4];
    const float* Wk = (const float*)d_in[5];
    const float* bk = (const float*)d_in[6];
    const float* Wv = (const float*)d_in[7];
    const float* bv = (const float*)d_in[8];
    const float* rel = (const float*)d_in[9];
    float* out = (float*)d_out;

    // QKV projections
    qkv_gemm<<<dim3(6, 16, 3), 256>>>(node_states, Wq, Wk, Wv, bq, bk, bv);

    // deterministic counting sort of edges by segment
    khist<<<NCHUNK, 256>>>(edge_idx);
    kcol<<<NSEG / 256, 256>>>();
    kscan<<<1, 1024>>>();
    kbase<<<NSEG / 256, 256>>>();
    kscatter<<<NCHUNK, CHUNK>>>(edge_idx);

    // per-edge relation logits
    kedge<<<Ee, 64>>>(edge_idx, rel);

    // per-segment softmax + aggregation
    kagg<<<NSEG, 128>>>(edge_idx, out);
}

// round 3
// speedup vs baseline: 1.2562x; 1.2562x over previous
#include <cuda_runtime.h>
#include <cuda_bf16.h>
#include <cstdint>

// Problem geometry (fixed)
#define Bb    4
#define Nn    512
#define Hh    12
#define Dh    64
#define HIDD  768
#define Ee    65536
#define NSEG  2048          // Bb*Nn segments
#define NCHUNK 256
#define CHUNK  256          // NCHUNK*CHUNK == Ee
#define CAP    512          // max edges per segment handled

#define XN (2048*768)
#define WN (768*768)

// ---------------- device scratch (static; no allocations allowed) ----------------
__device__ float g_Q[NSEG * HIDD];
__device__ float g_K[NSEG * HIDD];
__device__ float g_V[NSEG * HIDD];
__device__ float g_logits[Ee * Hh];
__device__ int   g_hist[NCHUNK * NSEG];
__device__ int   g_base[NCHUNK * NSEG];
__device__ int   g_cnt[NSEG];
__device__ int   g_start[NSEG + 1];
__device__ int   g_sorted[Ee];
// split-bf16 operands for tensor-core QKV
__device__ __nv_bfloat16 g_Xhi[XN];
__device__ __nv_bfloat16 g_Xlo[XN];
__device__ __nv_bfloat16 g_Whi[3 * WN];
__device__ __nv_bfloat16 g_Wlo[3 * WN];

// ---------------- helpers ----------------
__device__ __forceinline__ uint32_t smem_u32(const void* p) {
    uint32_t a;
    asm("{ .reg .u64 t; cvta.to.shared.u64 t, %1; cvt.u32.u64 %0, t; }" : "=r"(a) : "l"(p));
    return a;
}
__device__ __forceinline__ void ldmx4(uint32_t* r, uint32_t addr) {
    asm volatile("ldmatrix.sync.aligned.m8n8.x4.shared.b16 {%0,%1,%2,%3}, [%4];"
                 : "=r"(r[0]), "=r"(r[1]), "=r"(r[2]), "=r"(r[3]) : "r"(addr));
}
__device__ __forceinline__ void mma16816(float* c, const uint32_t* a, const uint32_t* b) {
    asm volatile("mma.sync.aligned.m16n8k16.row.col.f32.bf16.bf16.f32 "
                 "{%0,%1,%2,%3}, {%4,%5,%6,%7}, {%8,%9}, {%0,%1,%2,%3};"
                 : "+f"(c[0]), "+f"(c[1]), "+f"(c[2]), "+f"(c[3])
                 : "r"(a[0]), "r"(a[1]), "r"(a[2]), "r"(a[3]), "r"(b[0]), "r"(b[1]));
}

// ---------------- 0) split-bf16 conversion ----------------
__global__ void kconv(const float* __restrict__ x,
                      const float* __restrict__ wq, const float* __restrict__ wk,
                      const float* __restrict__ wv)
{
    int i = blockIdx.x * 256 + threadIdx.x;
    float v; __nv_bfloat16* hi; __nv_bfloat16* lo; int o;
    if (i < XN) {
        v = x[i]; hi = g_Xhi; lo = g_Xlo; o = i;
    } else {
        int j = i - XN;
        int w = j / WN; o = j - w * WN;
        v = (w == 0 ? wq : (w == 1 ? wk : wv))[o];
        hi = g_Whi + w * WN; lo = g_Wlo + w * WN;
    }
    __nv_bfloat16 h = __float2bfloat16(v);
    hi[o] = h;
    lo[o] = __float2bfloat16(v - __bfloat162float(h));
}

// ---------------- 1) QKV projection via mma.sync split-bf16 ----------------
// C[2048x768] = X @ W^T + b. Block 128x128, 8 warps (2x4), warp tile 64x32, BK=32.
#define ASTR 40   // padded bf16 row stride
__global__ __launch_bounds__(256, 2) void qkv_hmma(
    const float* __restrict__ bq, const float* __restrict__ bk, const float* __restrict__ bv)
{
    __shared__ __nv_bfloat16 sAh[128 * ASTR];
    __shared__ __nv_bfloat16 sAl[128 * ASTR];
    __shared__ __nv_bfloat16 sBh[128 * ASTR];
    __shared__ __nv_bfloat16 sBl[128 * ASTR];

    const int t = threadIdx.x;
    const int lane = t & 31;
    const int wid = t >> 5;
    const int wr = wid >> 2;        // 0..1  -> 64-row band
    const int wc = wid & 3;         // 0..3  -> 32-col band
    const int n0 = blockIdx.x * 128;
    const int m0 = blockIdx.y * 128;
    const int z  = blockIdx.z;

    const __nv_bfloat16* Wh = g_Whi + z * WN;
    const __nv_bfloat16* Wl = g_Wlo + z * WN;

    const uint32_t sAh_b = smem_u32(sAh);
    const uint32_t sAl_b = smem_u32(sAl);
    const uint32_t sBh_b = smem_u32(sBh);
    const uint32_t sBl_b = smem_u32(sBl);

    float acc[4][4][4];
    #pragma unroll
    for (int mi = 0; mi < 4; mi++)
        #pragma unroll
        for (int nj = 0; nj < 4; nj++)
            #pragma unroll
            for (int q = 0; q < 4; q++) acc[mi][nj][q] = 0.f;

    const int g  = lane >> 3;       // octet id 0..3
    const int rr = lane & 7;

    for (int kc = 0; kc < 24; kc++) {
        const int k0 = kc * 32;
        #pragma unroll
        for (int j = 0; j < 2; j++) {
            int li = t + 256 * j;        // 0..511
            int row = li >> 2;           // 0..127
            int f4  = li & 3;            // 0..3 (each = 8 bf16)
            int goff = row * HIDD + k0 + f4 * 8;
            int soff = row * ASTR + f4 * 8;
            *(float4*)&sAh[soff] = *(const float4*)(g_Xhi + (long)m0 * HIDD + goff);
            *(float4*)&sAl[soff] = *(const float4*)(g_Xlo + (long)m0 * HIDD + goff);
            *(float4*)&sBh[soff] = *(const float4*)(Wh + (long)n0 * HIDD + goff);
            *(float4*)&sBl[soff] = *(const float4*)(Wl + (long)n0 * HIDD + goff);
        }
        __syncthreads();

        #pragma unroll
        for (int ks = 0; ks < 2; ks++) {
            uint32_t af[4][4], bh[4][2], bl[4][2];
            // A hi fragments: octet g -> tile (rows +(g&1)*8, k +(g>>1)*8)
            const int acol = ks * 16 + (g >> 1) * 8;
            #pragma unroll
            for (int mi = 0; mi < 4; mi++) {
                int arow = wr * 64 + mi * 16 + (g & 1) * 8 + rr;
                ldmx4(af[mi], sAh_b + (uint32_t)(arow * ASTR + acol) * 2);
            }
            // B fragments: octet g -> tile (n +(g>>1)*8, k +(g&1)*8)
            const int bcol = ks * 16 + (g & 1) * 8;
            #pragma unroll
            for (int np = 0; np < 2; np++) {
                int brow = wc * 32 + np * 16 + (g >> 1) * 8 + rr;
                uint32_t tmp[4];
                ldmx4(tmp, sBh_b + (uint32_t)(brow * ASTR + bcol) * 2);
                bh[2 * np][0] = tmp[0]; bh[2 * np][1] = tmp[1];
                bh[2 * np + 1][0] = tmp[2]; bh[2 * np + 1][1] = tmp[3];
                ldmx4(tmp, sBl_b + (uint32_t)(brow * ASTR + bcol) * 2);
                bl[2 * np][0] = tmp[0]; bl[2 * np][1] = tmp[1];
                bl[2 * np + 1][0] = tmp[2]; bl[2 * np + 1][1] = tmp[3];
            }
            // hi*hi and hi*lo
            #pragma unroll
            for (int mi = 0; mi < 4; mi++)
                #pragma unroll
                for (int nj = 0; nj < 4; nj++) {
                    mma16816(acc[mi][nj], af[mi], bh[nj]);
                    mma16816(acc[mi][nj], af[mi], bl[nj]);
                }
            // lo*hi (reuse af registers)
            #pragma unroll
            for (int mi = 0; mi < 4; mi++) {
                int arow = wr * 64 + mi * 16 + (g & 1) * 8 + rr;
                ldmx4(af[mi], sAl_b + (uint32_t)(arow * ASTR + acol) * 2);
            }
            #pragma unroll
            for (int mi = 0; mi < 4; mi++)
                #pragma unroll
                for (int nj = 0; nj < 4; nj++)
                    mma16816(acc[mi][nj], af[mi], bh[nj]);
        }
        __syncthreads();
    }

    // epilogue: add bias, store fp32
    float* outp = (z == 0) ? g_Q : (z == 1) ? g_K : g_V;
    const float* bias = (z == 0) ? bq : (z == 1) ? bk : bv;
    #pragma unroll
    for (int mi = 0; mi < 4; mi++) {
        int row = m0 + wr * 64 + mi * 16 + (lane >> 2);
        #pragma unroll
        for (int nj = 0; nj < 4; nj++) {
            int col = n0 + wc * 32 + nj * 8 + (lane & 3) * 2;
            float b0 = bias[col], b1 = bias[col + 1];
            float2 v0 = make_float2(acc[mi][nj][0] + b0, acc[mi][nj][1] + b1);
            float2 v1 = make_float2(acc[mi][nj][2] + b0, acc[mi][nj][3] + b1);
            *(float2*)(outp + (long)row * HIDD + col) = v0;
            *(float2*)(outp + (long)(row + 8) * HIDD + col) = v1;
        }
    }
}

// ---------------- 2) deterministic counting sort by segment ----------------
__global__ void khist(const int* __restrict__ ei)
{
    __shared__ int cnt[NSEG];
    const int c = blockIdx.x;
    for (int i = threadIdx.x; i < NSEG; i += 256) cnt[i] = 0;
    __syncthreads();
    const int e = c * CHUNK + threadIdx.x;
    const int s = ei[e] * Nn + ei[Ee + e];
    atomicAdd(&cnt[s], 1);
    __syncthreads();
    for (int i = threadIdx.x; i < NSEG; i += 256) g_hist[c * NSEG + i] = cnt[i];
}

__global__ void kcol()
{
    const int s = blockIdx.x * 256 + threadIdx.x;
    int sum = 0;
    for (int c = 0; c < NCHUNK; c++) sum += g_hist[c * NSEG + s];
    g_cnt[s] = sum;
}

__global__ void kscan()
{
    __shared__ int bufA[NSEG];
    __shared__ int bufB[NSEG];
    const int t = threadIdx.x;   // 1024
    for (int i = t; i < NSEG; i += 1024) bufA[i] = g_cnt[i];
    __syncthreads();
    int* src = bufA; int* dst = bufB;
    for (int off = 1; off < NSEG; off <<= 1) {
        for (int i = t; i < NSEG; i += 1024)
            dst[i] = src[i] + ((i >= off) ? src[i - off] : 0);
        __syncthreads();
        int* tmp = src; src = dst; dst = tmp;
    }
    for (int i = t; i < NSEG; i += 1024) g_start[i + 1] = src[i];
    if (t == 0) g_start[0] = 0;
}

__global__ void kbase()
{
    const int s = blockIdx.x * 256 + threadIdx.x;
    int run = g_start[s];
    for (int c = 0; c < NCHUNK; c++) {
        g_base[c * NSEG + s] = run;
        run += g_hist[c * NSEG + s];
    }
}

__global__ void kscatter(const int* __restrict__ ei)
{
    __shared__ int segs[CHUNK];
    const int c = blockIdx.x;
    const int t = threadIdx.x;
    const int e = c * CHUNK + t;
    const int s = ei[e] * Nn + ei[Ee + e];
    segs[t] = s;
    __syncthreads();
    int rank = 0;
    for (int i = 0; i < t; i++) rank += (segs[i] == s);
    g_sorted[g_base[c * NSEG + s] + rank] = e;
}

// ---------------- 3) per-edge relation logits (fp32, FFMA) ----------------
__global__ __launch_bounds__(64) void kedge(const int* __restrict__ ei,
                                            const float* __restrict__ rel)
{
    __shared__ float Re[64 * 64];
    __shared__ float qs[HIDD];
    __shared__ float ks[HIDD];

    const int e = blockIdx.x;
    const int t = threadIdx.x;
    const int b  = ei[e];
    const int hn = ei[Ee + e];
    const int tn = ei[2 * Ee + e];
    const int r  = ei[3 * Ee + e];

    const float4* rp = (const float4*)(rel + (long)r * 4096);
    float4* Rp = (float4*)Re;
    #pragma unroll 4
    for (int i = t; i < 1024; i += 64) Rp[i] = rp[i];

    const float4* qp = (const float4*)(g_Q + (b * Nn + hn) * HIDD);
    const float4* kp = (const float4*)(g_K + (b * Nn + tn) * HIDD);
    float4* qd = (float4*)qs;
    float4* kd = (float4*)ks;
    #pragma unroll
    for (int i = t; i < 192; i += 64) { qd[i] = qp[i]; kd[i] = kp[i]; }
    __syncthreads();

    const int hg = t >> 4;       // 0..3
    const int kq = t & 15;       // 0..15
    const int k0 = kq * 4;

    float acc[3][4];
    #pragma unroll
    for (int j = 0; j < 3; j++)
        #pragma unroll
        for (int v = 0; v < 4; v++) acc[j][v] = 0.f;

    #pragma unroll
    for (int d0 = 0; d0 < 64; d0 += 4) {
        float qa[3][4];
        #pragma unroll
        for (int j = 0; j < 3; j++) {
            float4 qv = *(const float4*)&qs[(hg + 4 * j) * 64 + d0];
            qa[j][0] = qv.x; qa[j][1] = qv.y; qa[j][2] = qv.z; qa[j][3] = qv.w;
        }
        #pragma unroll
        for (int dd = 0; dd < 4; dd++) {
            float4 rv = *(const float4*)&Re[(d0 + dd) * 64 + k0];
            #pragma unroll
            for (int j = 0; j < 3; j++) {
                acc[j][0] += qa[j][dd] * rv.x;
                acc[j][1] += qa[j][dd] * rv.y;
                acc[j][2] += qa[j][dd] * rv.z;
                acc[j][3] += qa[j][dd] * rv.w;
            }
        }
    }

    float part[3];
    #pragma unroll
    for (int j = 0; j < 3; j++) {
        float4 kv = *(const float4*)&ks[(hg + 4 * j) * 64 + k0];
        part[j] = acc[j][0] * kv.x + acc[j][1] * kv.y + acc[j][2] * kv.z + acc[j][3] * kv.w;
    }
    #pragma unroll
    for (int off = 8; off; off >>= 1) {
        #pragma unroll
        for (int j = 0; j < 3; j++)
            part[j] += __shfl_down_sync(0xffffffffu, part[j], off, 16);
    }
    if (kq == 0) {
        #pragma unroll
        for (int j = 0; j < 3; j++)
            g_logits[e * Hh + hg + 4 * j] = part[j] * 0.125f;  // / sqrt(64)
    }
}

// ---------------- 4) per-segment softmax + V aggregation ----------------
__global__ __launch_bounds__(128) void kagg(const int* __restrict__ ei,
                                            float* __restrict__ out)
{
    __shared__ float    exb[CAP * Hh];   // 24 KB
    __shared__ int      voff[CAP];       // 2 KB
    __shared__ unsigned umax[Hh];
    __shared__ float    mx[Hh], dnm[Hh];

    const int s = blockIdx.x;
    const int t = threadIdx.x;
    const int beg = g_start[s];
    int cnt = g_start[s + 1] - beg;
    if (cnt > CAP) cnt = CAP;
    float* orow = out + s * HIDD;

    if (cnt == 0) {
        #pragma unroll
        for (int j = 0; j < 6; j++) orow[t + 128 * j] = 0.f;
        return;
    }

    if (t < Hh) umax[t] = 0u;
    __syncthreads();

    for (int i = t; i < cnt; i += 128) {
        int e = g_sorted[beg + i];
        voff[i] = (ei[e] * Nn + ei[2 * Ee + e]) * HIDD;
    }
    for (int j = t; j < cnt * Hh; j += 128) {
        int i = j / Hh;
        int h = j - i * Hh;
        int e = g_sorted[beg + i];
        float l = g_logits[e * Hh + h];
        exb[j] = l;
        unsigned bits = __float_as_uint(l);
        unsigned key  = (bits & 0x80000000u) ? ~bits : (bits | 0x80000000u);
        atomicMax(&umax[h], key);   // max is order-independent -> deterministic
    }
    __syncthreads();

    if (t < Hh) {
        unsigned key  = umax[t];
        unsigned bits = (key & 0x80000000u) ? (key & 0x7fffffffu) : ~key;
        mx[t] = __uint_as_float(bits);
    }
    __syncthreads();

    for (int j = t; j < cnt * Hh; j += 128) {
        int h = j % Hh;
        exb[j] = __expf(exb[j] - mx[h]);
    }
    __syncthreads();

    const int w = t >> 5, lane = t & 31;
    #pragma unroll
    for (int jj = 0; jj < 3; jj++) {
        int h = w * 3 + jj;
        float p = 0.f;
        for (int i = lane; i < cnt; i += 32) p += exb[i * Hh + h];
        #pragma unroll
        for (int off = 16; off; off >>= 1) p += __shfl_xor_sync(0xffffffffu, p, off);
        if (lane == 0) dnm[h] = p;
    }
    __syncthreads();

    float rd[6], accr[6];
    int hcol[6];
    #pragma unroll
    for (int j = 0; j < 6; j++) {
        int c = t + 128 * j;
        hcol[j] = c >> 6;
        rd[j] = 1.f / dnm[hcol[j]];
        accr[j] = 0.f;
    }
    for (int i = 0; i < cnt; i++) {
        const float* vrow = g_V + voff[i];
        const float* exr  = &exb[i * Hh];
        #pragma unroll
        for (int j = 0; j < 6; j++) {
            float p = exr[hcol[j]] * rd[j];
            accr[j] += p * vrow[t + 128 * j];
        }
    }
    #pragma unroll
    for (int j = 0; j < 6; j++) orow[t + 128 * j] = accr[j];
}

// ---------------- launch ----------------
extern "C" void kernel_launch(void* const* d_in, const int* in_sizes, int n_in,
                              void* d_out, int out_size)
{
    const float* node_states = (const float*)d_in[0];
    const int*   edge_idx    = (const int*)  d_in[1];
    // d_in[2] = node_type_ids (unused)
    const float* Wq = (const float*)d_in[3];
    const float* bq = (const float*)d_in[4];
    const float* Wk = (const float*)d_in[5];
    const float* bk = (const float*)d_in[6];
    const float* Wv = (const float*)d_in[7];
    const float* bv = (const float*)d_in[8];
    const float* rel = (const float*)d_in[9];
    float* out = (float*)d_out;

    // split-bf16 conversion of X and W
    kconv<<<(XN + 3 * WN) / 256, 256>>>(node_states, Wq, Wk, Wv);

    // QKV projections on tensor cores (mma.sync HMMA)
    qkv_hmma<<<dim3(6, 16, 3), 256>>>(bq, bk, bv);

    // deterministic counting sort of edges by segment
    khist<<<NCHUNK, 256>>>(edge_idx);
    kcol<<<NSEG / 256, 256>>>();
    kscan<<<1, 1024>>>();
    kbase<<<NSEG / 256, 256>>>();
    kscatter<<<NCHUNK, CHUNK>>>(edge_idx);

    // per-edge relation logits
    kedge<<<Ee, 64>>>(edge_idx, rel);

    // per-segment softmax + aggregation
    kagg<<<NSEG, 128>>>(edge_idx, out);
}

// round 4
// speedup vs baseline: 1.7551x; 1.3972x over previous
#include <cuda_runtime.h>
#include <cuda_bf16.h>
#include <cstdint>

// Problem geometry (fixed)
#define Bb    4
#define Nn    512
#define Hh    12
#define Dh    64
#define HIDD  768
#define Ee    65536
#define NSEG  2048          // Bb*Nn segments
#define NREL  64
#define NCHUNK 256
#define CHUNK  256          // NCHUNK*CHUNK == Ee
#define CAP    512          // max edges per segment handled

#define XN (2048*768)
#define WN (768*768)

// ---------------- device scratch (static; no allocations allowed) ----------------
__device__ float g_K[NSEG * HIDD];
__device__ float g_V[NSEG * HIDD];
__device__ float g_logits[Ee * Hh];
__device__ int   g_hist[NCHUNK * NSEG];
__device__ int   g_base[NCHUNK * NSEG];
__device__ int   g_cnt[NSEG];
__device__ int   g_start[NSEG + 1];
__device__ int   g_sorted[Ee];
// relation sort
__device__ int   g_rhist[NCHUNK * NREL];
__device__ int   g_rbase[NCHUNK * NREL];
__device__ int   g_rstart[NREL + 1];
__device__ int   g_rsorted[Ee];
// split-bf16 operands
__device__ __nv_bfloat16 g_Xhi[XN];
__device__ __nv_bfloat16 g_Xlo[XN];
__device__ __nv_bfloat16 g_Whi[3 * WN];
__device__ __nv_bfloat16 g_Wlo[3 * WN];
__device__ __nv_bfloat16 g_Qhi[NSEG * HIDD];
__device__ __nv_bfloat16 g_Qlo[NSEG * HIDD];
__device__ __nv_bfloat16 g_Rhi[NREL * 4096];   // transposed: [r][n][k]
__device__ __nv_bfloat16 g_Rlo[NREL * 4096];

// ---------------- helpers ----------------
__device__ __forceinline__ uint32_t smem_u32(const void* p) {
    uint32_t a;
    asm("{ .reg .u64 t; cvta.to.shared.u64 t, %1; cvt.u32.u64 %0, t; }" : "=r"(a) : "l"(p));
    return a;
}
__device__ __forceinline__ void ldmx4(uint32_t* r, uint32_t addr) {
    asm volatile("ldmatrix.sync.aligned.m8n8.x4.shared.b16 {%0,%1,%2,%3}, [%4];"
                 : "=r"(r[0]), "=r"(r[1]), "=r"(r[2]), "=r"(r[3]) : "r"(addr));
}
__device__ __forceinline__ void mma16816(float* c, const uint32_t* a, const uint32_t* b) {
    asm volatile("mma.sync.aligned.m16n8k16.row.col.f32.bf16.bf16.f32 "
                 "{%0,%1,%2,%3}, {%4,%5,%6,%7}, {%8,%9}, {%0,%1,%2,%3};"
                 : "+f"(c[0]), "+f"(c[1]), "+f"(c[2]), "+f"(c[3])
                 : "r"(a[0]), "r"(a[1]), "r"(a[2]), "r"(a[3]), "r"(b[0]), "r"(b[1]));
}

// ---------------- 0) split-bf16 conversion (X, W, R^T) ----------------
__global__ void kconv(const float* __restrict__ x,
                      const float* __restrict__ wq, const float* __restrict__ wk,
                      const float* __restrict__ wv, const float* __restrict__ rel)
{
    int i = blockIdx.x * 256 + threadIdx.x;
    float v; __nv_bfloat16* hi; __nv_bfloat16* lo; int o;
    if (i < XN) {
        v = x[i]; hi = g_Xhi; lo = g_Xlo; o = i;
    } else if (i < XN + 3 * WN) {
        int j = i - XN;
        int w = j / WN; o = j - w * WN;
        v = (w == 0 ? wq : (w == 1 ? wk : wv))[o];
        hi = g_Whi + w * WN; lo = g_Wlo + w * WN;
    } else {
        int j = i - XN - 3 * WN;          // 0..NREL*4096
        int r = j >> 12;
        int rem = j & 4095;
        int kk = rem >> 6;
        int nn = rem & 63;
        v = rel[j];
        o = (r << 12) + nn * 64 + kk;     // transposed store
        hi = g_Rhi; lo = g_Rlo;
    }
    __nv_bfloat16 h = __float2bfloat16(v);
    hi[o] = h;
    lo[o] = __float2bfloat16(v - __bfloat162float(h));
}

// ---------------- 1) QKV projection via mma.sync split-bf16 ----------------
#define ASTR 40   // padded bf16 row stride
__global__ __launch_bounds__(256, 2) void qkv_hmma(
    const float* __restrict__ bq, const float* __restrict__ bk, const float* __restrict__ bv)
{
    __shared__ __nv_bfloat16 sAh[128 * ASTR];
    __shared__ __nv_bfloat16 sAl[128 * ASTR];
    __shared__ __nv_bfloat16 sBh[128 * ASTR];
    __shared__ __nv_bfloat16 sBl[128 * ASTR];

    const int t = threadIdx.x;
    const int lane = t & 31;
    const int wid = t >> 5;
    const int wr = wid >> 2;        // 0..1  -> 64-row band
    const int wc = wid & 3;         // 0..3  -> 32-col band
    const int n0 = blockIdx.x * 128;
    const int m0 = blockIdx.y * 128;
    const int z  = blockIdx.z;

    const __nv_bfloat16* Wh = g_Whi + z * WN;
    const __nv_bfloat16* Wl = g_Wlo + z * WN;

    const uint32_t sAh_b = smem_u32(sAh);
    const uint32_t sAl_b = smem_u32(sAl);
    const uint32_t sBh_b = smem_u32(sBh);
    const uint32_t sBl_b = smem_u32(sBl);

    float acc[4][4][4];
    #pragma unroll
    for (int mi = 0; mi < 4; mi++)
        #pragma unroll
        for (int nj = 0; nj < 4; nj++)
            #pragma unroll
            for (int q = 0; q < 4; q++) acc[mi][nj][q] = 0.f;

    const int g  = lane >> 3;       // octet id 0..3
    const int rr = lane & 7;

    for (int kc = 0; kc < 24; kc++) {
        const int k0 = kc * 32;
        #pragma unroll
        for (int j = 0; j < 2; j++) {
            int li = t + 256 * j;        // 0..511
            int row = li >> 2;           // 0..127
            int f4  = li & 3;            // 0..3 (each = 8 bf16)
            int goff = row * HIDD + k0 + f4 * 8;
            int soff = row * ASTR + f4 * 8;
            *(float4*)&sAh[soff] = *(const float4*)(g_Xhi + (long)m0 * HIDD + goff);
            *(float4*)&sAl[soff] = *(const float4*)(g_Xlo + (long)m0 * HIDD + goff);
            *(float4*)&sBh[soff] = *(const float4*)(Wh + (long)n0 * HIDD + goff);
            *(float4*)&sBl[soff] = *(const float4*)(Wl + (long)n0 * HIDD + goff);
        }
        __syncthreads();

        #pragma unroll
        for (int ks = 0; ks < 2; ks++) {
            uint32_t af[4][4], bh[4][2], bl[4][2];
            const int acol = ks * 16 + (g >> 1) * 8;
            #pragma unroll
            for (int mi = 0; mi < 4; mi++) {
                int arow = wr * 64 + mi * 16 + (g & 1) * 8 + rr;
                ldmx4(af[mi], sAh_b + (uint32_t)(arow * ASTR + acol) * 2);
            }
            const int bcol = ks * 16 + (g & 1) * 8;
            #pragma unroll
            for (int np = 0; np < 2; np++) {
                int brow = wc * 32 + np * 16 + (g >> 1) * 8 + rr;
                uint32_t tmp[4];
                ldmx4(tmp, sBh_b + (uint32_t)(brow * ASTR + bcol) * 2);
                bh[2 * np][0] = tmp[0]; bh[2 * np][1] = tmp[1];
                bh[2 * np + 1][0] = tmp[2]; bh[2 * np + 1][1] = tmp[3];
                ldmx4(tmp, sBl_b + (uint32_t)(brow * ASTR + bcol) * 2);
                bl[2 * np][0] = tmp[0]; bl[2 * np][1] = tmp[1];
                bl[2 * np + 1][0] = tmp[2]; bl[2 * np + 1][1] = tmp[3];
            }
            #pragma unroll
            for (int mi = 0; mi < 4; mi++)
                #pragma unroll
                for (int nj = 0; nj < 4; nj++) {
                    mma16816(acc[mi][nj], af[mi], bh[nj]);
                    mma16816(acc[mi][nj], af[mi], bl[nj]);
                }
            #pragma unroll
            for (int mi = 0; mi < 4; mi++) {
                int arow = wr * 64 + mi * 16 + (g & 1) * 8 + rr;
                ldmx4(af[mi], sAl_b + (uint32_t)(arow * ASTR + acol) * 2);
            }
            #pragma unroll
            for (int mi = 0; mi < 4; mi++)
                #pragma unroll
                for (int nj = 0; nj < 4; nj++)
                    mma16816(acc[mi][nj], af[mi], bh[nj]);
        }
        __syncthreads();
    }

    // epilogue
    const float* bias = (z == 0) ? bq : (z == 1) ? bk : bv;
    #pragma unroll
    for (int mi = 0; mi < 4; mi++) {
        int row = m0 + wr * 64 + mi * 16 + (lane >> 2);
        #pragma unroll
        for (int nj = 0; nj < 4; nj++) {
            int col = n0 + wc * 32 + nj * 8 + (lane & 3) * 2;
            float b0 = bias[col], b1 = bias[col + 1];
            float v00 = acc[mi][nj][0] + b0, v01 = acc[mi][nj][1] + b1;
            float v10 = acc[mi][nj][2] + b0, v11 = acc[mi][nj][3] + b1;
            if (z == 0) {
                // Q -> split bf16 (consumed by relation GEMM)
                __nv_bfloat16 h00 = __float2bfloat16(v00), h01 = __float2bfloat16(v01);
                __nv_bfloat16 h10 = __float2bfloat16(v10), h11 = __float2bfloat16(v11);
                __nv_bfloat162 hi0; hi0.x = h00; hi0.y = h01;
                __nv_bfloat162 hi1; hi1.x = h10; hi1.y = h11;
                __nv_bfloat162 lo0; lo0.x = __float2bfloat16(v00 - __bfloat162float(h00));
                                    lo0.y = __float2bfloat16(v01 - __bfloat162float(h01));
                __nv_bfloat162 lo1; lo1.x = __float2bfloat16(v10 - __bfloat162float(h10));
                                    lo1.y = __float2bfloat16(v11 - __bfloat162float(h11));
                *(__nv_bfloat162*)(g_Qhi + (long)row * HIDD + col) = hi0;
                *(__nv_bfloat162*)(g_Qhi + (long)(row + 8) * HIDD + col) = hi1;
                *(__nv_bfloat162*)(g_Qlo + (long)row * HIDD + col) = lo0;
                *(__nv_bfloat162*)(g_Qlo + (long)(row + 8) * HIDD + col) = lo1;
            } else {
                float* outp = (z == 1) ? g_K : g_V;
                *(float2*)(outp + (long)row * HIDD + col) = make_float2(v00, v01);
                *(float2*)(outp + (long)(row + 8) * HIDD + col) = make_float2(v10, v11);
            }
        }
    }
}

// ---------------- 2) deterministic counting sorts ----------------
__global__ void khist(const int* __restrict__ ei)
{
    __shared__ int cnt[NSEG];
    const int c = blockIdx.x;
    for (int i = threadIdx.x; i < NSEG; i += 256) cnt[i] = 0;
    __syncthreads();
    const int e = c * CHUNK + threadIdx.x;
    const int s = ei[e] * Nn + ei[Ee + e];
    atomicAdd(&cnt[s], 1);
    __syncthreads();
    for (int i = threadIdx.x; i < NSEG; i += 256) g_hist[c * NSEG + i] = cnt[i];
}

// warp-per-segment: per-chunk exclusive prefix (into g_base) + totals (g_cnt)
__global__ void kbasewarp()
{
    const int t = threadIdx.x;
    const int s = blockIdx.x * 8 + (t >> 5);
    const int lane = t & 31;
    int v[8]; int sum = 0;
    #pragma unroll
    for (int i = 0; i < 8; i++) {
        v[i] = g_hist[(lane * 8 + i) * NSEG + s];
        sum += v[i];
    }
    int ex = sum;
    #pragma unroll
    for (int off = 1; off < 32; off <<= 1) {
        int n = __shfl_up_sync(0xffffffffu, ex, off);
        if (lane >= off) ex += n;
    }
    int run = ex - sum;   // exclusive base for this lane's 8 chunks
    #pragma unroll
    for (int i = 0; i < 8; i++) {
        g_base[(lane * 8 + i) * NSEG + s] = run;
        run += v[i];
    }
    if (lane == 31) g_cnt[s] = run;
}

__global__ void kscan()
{
    __shared__ int bufA[NSEG];
    __shared__ int bufB[NSEG];
    const int t = threadIdx.x;   // 1024
    for (int i = t; i < NSEG; i += 1024) bufA[i] = g_cnt[i];
    __syncthreads();
    int* src = bufA; int* dst = bufB;
    for (int off = 1; off < NSEG; off <<= 1) {
        for (int i = t; i < NSEG; i += 1024)
            dst[i] = src[i] + ((i >= off) ? src[i - off] : 0);
        __syncthreads();
        int* tmp = src; src = dst; dst = tmp;
    }
    for (int i = t; i < NSEG; i += 1024) g_start[i + 1] = src[i];
    if (t == 0) g_start[0] = 0;
}

__global__ void kscatter(const int* __restrict__ ei)
{
    __shared__ int segs[CHUNK];
    const int c = blockIdx.x;
    const int t = threadIdx.x;
    const int e = c * CHUNK + t;
    const int s = ei[e] * Nn + ei[Ee + e];
    segs[t] = s;
    __syncthreads();
    int rank = 0;
    for (int i = 0; i < t; i++) rank += (segs[i] == s);
    g_sorted[g_start[s] + g_base[c * NSEG + s] + rank] = e;
}

// relation sort (64 bins)
__global__ void rhist(const int* __restrict__ ei)
{
    __shared__ int cnt[NREL];
    const int c = blockIdx.x;
    const int t = threadIdx.x;
    if (t < NREL) cnt[t] = 0;
    __syncthreads();
    atomicAdd(&cnt[ei[3 * Ee + c * CHUNK + t]], 1);
    __syncthreads();
    if (t < NREL) g_rhist[c * NREL + t] = cnt[t];
}

__global__ void rprep()
{
    __shared__ int tot[NREL];
    const int t = threadIdx.x;   // 64 threads
    if (t < NREL) {
        int run = 0;
        for (int c = 0; c < NCHUNK; c++) {
            g_rbase[c * NREL + t] = run;
            run += g_rhist[c * NREL + t];
        }
        tot[t] = run;
    }
    __syncthreads();
    if (t == 0) {
        int s = 0;
        for (int i = 0; i < NREL; i++) { g_rstart[i] = s; s += tot[i]; }
        g_rstart[NREL] = s;
    }
}

__global__ void rscatter(const int* __restrict__ ei)
{
    __shared__ int rels[CHUNK];
    const int c = blockIdx.x;
    const int t = threadIdx.x;
    const int e = c * CHUNK + t;
    const int r = ei[3 * Ee + e];
    rels[t] = r;
    __syncthreads();
    int rank = 0;
    for (int i = 0; i < t; i++) rank += (rels[i] == r);
    g_rsorted[g_rstart[r] + g_rbase[c * NREL + r] + rank] = e;
}

// ---------------- 3) relation-batched logits on tensor cores ----------------
// Per relation r: A = gathered q rows [(e,h) x 64] (split bf16), B = R_r^T [n=64][k=64],
// C = Qp; epilogue: logits[e,h] = dot(Qp_row, K_row)/8 in fp32.
#define RSTR 72   // bf16 elem stride (144B rows -> conflict-free ldmatrix)
#define KSTR 68   // f32 elem stride (16B-aligned, staggered banks)
#define EDGE_SMEM (18432 + 18432 + 34816 + 9216 + 9216 + 192)
__global__ __launch_bounds__(256) void kedge2(const int* __restrict__ ei)
{
    extern __shared__ __align__(16) char sm[];
    __nv_bfloat16* sAh = (__nv_bfloat16*)(sm);
    __nv_bfloat16* sAl = (__nv_bfloat16*)(sm + 18432);
    float*         sK  = (float*)(sm + 36864);
    __nv_bfloat16* sRh = (__nv_bfloat16*)(sm + 71680);
    __nv_bfloat16* sRl = (__nv_bfloat16*)(sm + 80896);
    int* qoff = (int*)(sm + 90112);
    int* koff = qoff + 12;
    int* eidv = koff + 12;

    const int r  = blockIdx.x;
    const int t  = threadIdx.x;
    const int rs = g_rstart[r];
    const int total = (g_rstart[r + 1] - rs) * Hh;   // rows in this relation group
    const int j0 = blockIdx.y * 128;
    if (j0 >= total) return;

    const int e_first = j0 / Hh;
    const int jlast = min(j0 + 127, total - 1);
    const int nloc = jlast / Hh - e_first + 1;       // <= 12

    if (t < nloc) {
        int e = g_rsorted[rs + e_first + t];
        int b = ei[e], hn = ei[Ee + e], tn = ei[2 * Ee + e];
        qoff[t] = (b * Nn + hn) * HIDD;
        koff[t] = (b * Nn + tn) * HIDD;
        eidv[t] = e;
    }
    {
        const __nv_bfloat16* Rh = g_Rhi + (r << 12);
        const __nv_bfloat16* Rl = g_Rlo + (r << 12);
        #pragma unroll
        for (int i = t; i < 512; i += 256) {
            int n = i >> 3, f = i & 7;
            *(float4*)&sRh[n * RSTR + f * 8] = *(const float4*)&Rh[n * 64 + f * 8];
            *(float4*)&sRl[n * RSTR + f * 8] = *(const float4*)&Rl[n * 64 + f * 8];
        }
    }
    __syncthreads();

    // gather A (hi/lo) rows and K rows
    #pragma unroll
    for (int i = t; i < 1024; i += 256) {
        int row = i >> 3, f = i & 7;
        int j = j0 + row; if (j > total - 1) j = total - 1;
        int le = j / Hh - e_first;
        int h = j % Hh;
        int off = qoff[le] + h * 64 + f * 8;
        *(float4*)&sAh[row * RSTR + f * 8] = *(const float4*)&g_Qhi[off];
        *(float4*)&sAl[row * RSTR + f * 8] = *(const float4*)&g_Qlo[off];
    }
    #pragma unroll
    for (int i = t; i < 2048; i += 256) {
        int row = i >> 4, f = i & 15;
        int j = j0 + row; if (j > total - 1) j = total - 1;
        int le = j / Hh - e_first;
        int h = j % Hh;
        *(float4*)&sK[row * KSTR + f * 4] = *(const float4*)&g_K[koff[le] + h * 64 + f * 4];
    }
    __syncthreads();

    const int lane = t & 31;
    const int wm = t >> 5;          // warp -> rows wm*16..+15
    const int g = lane >> 3, rr = lane & 7;
    const uint32_t sAh_b = smem_u32(sAh), sAl_b = smem_u32(sAl);
    const uint32_t sRh_b = smem_u32(sRh), sRl_b = smem_u32(sRl);

    float acc[8][4];
    #pragma unroll
    for (int nt = 0; nt < 8; nt++)
        #pragma unroll
        for (int q = 0; q < 4; q++) acc[nt][q] = 0.f;

    #pragma unroll
    for (int ks = 0; ks < 4; ks++) {
        uint32_t bh[8][2], bl[8][2], af[4];
        const int bcol = ks * 16 + (g & 1) * 8;
        #pragma unroll
        for (int np = 0; np < 4; np++) {
            int brow = np * 16 + (g >> 1) * 8 + rr;
            uint32_t tmp[4];
            ldmx4(tmp, sRh_b + (uint32_t)(brow * RSTR + bcol) * 2);
            bh[2 * np][0] = tmp[0]; bh[2 * np][1] = tmp[1];
            bh[2 * np + 1][0] = tmp[2]; bh[2 * np + 1][1] = tmp[3];
            ldmx4(tmp, sRl_b + (uint32_t)(brow * RSTR + bcol) * 2);
            bl[2 * np][0] = tmp[0]; bl[2 * np][1] = tmp[1];
            bl[2 * np + 1][0] = tmp[2]; bl[2 * np + 1][1] = tmp[3];
        }
        const int acol = ks * 16 + (g >> 1) * 8;
        const int arow = wm * 16 + (g & 1) * 8 + rr;
        ldmx4(af, sAh_b + (uint32_t)(arow * RSTR + acol) * 2);
        #pragma unroll
        for (int nt = 0; nt < 8; nt++) {
            mma16816(acc[nt], af, bh[nt]);
            mma16816(acc[nt], af, bl[nt]);
        }
        ldmx4(af, sAl_b + (uint32_t)(arow * RSTR + acol) * 2);
        #pragma unroll
        for (int nt = 0; nt < 8; nt++)
            mma16816(acc[nt], af, bh[nt]);
    }

    // epilogue: dot Qp rows with K rows (fp32)
    const int rlo = wm * 16 + (lane >> 2);
    const int rhi = rlo + 8;
    float slo = 0.f, shi = 0.f;
    #pragma unroll
    for (int nt = 0; nt < 8; nt++) {
        int col = nt * 8 + (lane & 3) * 2;
        slo += acc[nt][0] * sK[rlo * KSTR + col] + acc[nt][1] * sK[rlo * KSTR + col + 1];
        shi += acc[nt][2] * sK[rhi * KSTR + col] + acc[nt][3] * sK[rhi * KSTR + col + 1];
    }
    slo += __shfl_xor_sync(0xffffffffu, slo, 1);
    slo += __shfl_xor_sync(0xffffffffu, slo, 2);
    shi += __shfl_xor_sync(0xffffffffu, shi, 1);
    shi += __shfl_xor_sync(0xffffffffu, shi, 2);
    if ((lane & 3) == 0) {
        int j = j0 + rlo;
        if (j < total) {
            int le = j / Hh - e_first;
            g_logits[eidv[le] * Hh + (j % Hh)] = slo * 0.125f;
        }
        j = j0 + rhi;
        if (j < total) {
            int le = j / Hh - e_first;
            g_logits[eidv[le] * Hh + (j % Hh)] = shi * 0.125f;
        }
    }
}

// ---------------- 4) per-segment softmax + V aggregation ----------------
__global__ __launch_bounds__(128) void kagg(const int* __restrict__ ei,
                                            float* __restrict__ out)
{
    __shared__ float    exb[CAP * Hh];   // 24 KB
    __shared__ int      voff[CAP];       // 2 KB
    __shared__ unsigned umax[Hh];
    __shared__ float    mx[Hh], dnm[Hh];

    const int s = blockIdx.x;
    const int t = threadIdx.x;
    const int beg = g_start[s];
    int cnt = g_start[s + 1] - beg;
    if (cnt > CAP) cnt = CAP;
    float* orow = out + s * HIDD;

    if (cnt == 0) {
        #pragma unroll
        for (int j = 0; j < 6; j++) orow[t + 128 * j] = 0.f;
        return;
    }

    if (t < Hh) umax[t] = 0u;
    __syncthreads();

    for (int i = t; i < cnt; i += 128) {
        int e = g_sorted[beg + i];
        voff[i] = (ei[e] * Nn + ei[2 * Ee + e]) * HIDD;
    }
    for (int j = t; j < cnt * Hh; j += 128) {
        int i = j / Hh;
        int h = j - i * Hh;
        int e = g_sorted[beg + i];
        float l = g_logits[e * Hh + h];
        exb[j] = l;
        unsigned bits = __float_as_uint(l);
        unsigned key  = (bits & 0x80000000u) ? ~bits : (bits | 0x80000000u);
        atomicMax(&umax[h], key);   // order-independent -> deterministic
    }
    __syncthreads();

    if (t < Hh) {
        unsigned key  = umax[t];
        unsigned bits = (key & 0x80000000u) ? (key & 0x7fffffffu) : ~key;
        mx[t] = __uint_as_float(bits);
    }
    __syncthreads();

    for (int j = t; j < cnt * Hh; j += 128) {
        int h = j % Hh;
        exb[j] = __expf(exb[j] - mx[h]);
    }
    __syncthreads();

    const int w = t >> 5, lane = t & 31;
    #pragma unroll
    for (int jj = 0; jj < 3; jj++) {
        int h = w * 3 + jj;
        float p = 0.f;
        for (int i = lane; i < cnt; i += 32) p += exb[i * Hh + h];
        #pragma unroll
        for (int off = 16; off; off >>= 1) p += __shfl_xor_sync(0xffffffffu, p, off);
        if (lane == 0) dnm[h] = p;
    }
    __syncthreads();

    float rd[6], accr[6];
    int hcol[6];
    #pragma unroll
    for (int j = 0; j < 6; j++) {
        int c = t + 128 * j;
        hcol[j] = c >> 6;
        rd[j] = 1.f / dnm[hcol[j]];
        accr[j] = 0.f;
    }
    for (int i = 0; i < cnt; i++) {
        const float* vrow = g_V + voff[i];
        const float* exr  = &exb[i * Hh];
        #pragma unroll
        for (int j = 0; j < 6; j++) {
            float p = exr[hcol[j]] * rd[j];
            accr[j] += p * vrow[t + 128 * j];
        }
    }
    #pragma unroll
    for (int j = 0; j < 6; j++) orow[t + 128 * j] = accr[j];
}

// ---------------- launch ----------------
extern "C" void kernel_launch(void* const* d_in, const int* in_sizes, int n_in,
                              void* d_out, int out_size)
{
    const float* node_states = (const float*)d_in[0];
    const int*   edge_idx    = (const int*)  d_in[1];
    // d_in[2] = node_type_ids (unused)
    const float* Wq = (const float*)d_in[3];
    const float* bq = (const float*)d_in[4];
    const float* Wk = (const float*)d_in[5];
    const float* bk = (const float*)d_in[6];
    const float* Wv = (const float*)d_in[7];
    const float* bv = (const float*)d_in[8];
    const float* rel = (const float*)d_in[9];
    float* out = (float*)d_out;

    static bool attr_done = false;
    if (!attr_done) {
        cudaFuncSetAttribute(kedge2, cudaFuncAttributeMaxDynamicSharedMemorySize, EDGE_SMEM);
        attr_done = true;
    }

    // split-bf16 conversion of X, W, R^T
    kconv<<<(XN + 3 * WN + NREL * 4096) / 256, 256>>>(node_states, Wq, Wk, Wv, rel);

    // QKV projections on tensor cores
    qkv_hmma<<<dim3(6, 16, 3), 256>>>(bq, bk, bv);

    // deterministic counting sort by segment
    khist<<<NCHUNK, 256>>>(edge_idx);
    kbasewarp<<<NSEG / 8, 256>>>();
    kscan<<<1, 1024>>>();
    kscatter<<<NCHUNK, CHUNK>>>(edge_idx);

    // deterministic counting sort by relation
    rhist<<<NCHUNK, 256>>>(edge_idx);
    rprep<<<1, 64>>>();
    rscatter<<<NCHUNK, CHUNK>>>(edge_idx);

    // relation-batched logits on tensor cores
    kedge2<<<dim3(NREL, 120), 256, EDGE_SMEM>>>(edge_idx);

    // per-segment softmax + aggregation
    kagg<<<NSEG, 128>>>(edge_idx, out);
}

// round 6
// speedup vs baseline: 1.8904x; 1.0771x over previous
#include <cuda_runtime.h>
#include <cuda_bf16.h>
#include <cstdint>

// Problem geometry (fixed)
#define Bb    4
#define Nn    512
#define Hh    12
#define Dh    64
#define HIDD  768
#define Ee    65536
#define NSEG  2048          // Bb*Nn segments
#define NREL  64
#define NCHUNK 256
#define CHUNK  256          // NCHUNK*CHUNK == Ee
#define CAP    512          // max edges per segment handled

#define XN (2048*768)
#define WN (768*768)

// ---------------- device scratch (static; no allocations allowed) ----------------
__device__ float g_K[NSEG * HIDD];
__device__ float g_V[NSEG * HIDD];
__device__ float g_logits[Ee * Hh];
__device__ unsigned short g_hist[NCHUNK * NSEG];
__device__ unsigned short g_base[NCHUNK * NSEG];
__device__ int   g_cnt[NSEG];
__device__ int   g_start[NSEG + 1];
__device__ int   g_sorted[Ee];
// relation sort
__device__ unsigned short g_rhist[NCHUNK * NREL];
__device__ unsigned short g_rbase[NCHUNK * NREL];
__device__ int   g_rstart[NREL + 1];
__device__ int   g_rsorted[Ee];
// split-bf16 operands
__device__ __nv_bfloat16 g_Xhi[XN];
__device__ __nv_bfloat16 g_Xlo[XN];
__device__ __nv_bfloat16 g_Whi[3 * WN];
__device__ __nv_bfloat16 g_Wlo[3 * WN];
__device__ __nv_bfloat16 g_Qhi[NSEG * HIDD];
__device__ __nv_bfloat16 g_Qlo[NSEG * HIDD];
__device__ __nv_bfloat16 g_Rhi[NREL * 4096];   // transposed: [r][n][k]
__device__ __nv_bfloat16 g_Rlo[NREL * 4096];

// ---------------- helpers ----------------
__device__ __forceinline__ uint32_t smem_u32(const void* p) {
    uint32_t a;
    asm("{ .reg .u64 t; cvta.to.shared.u64 t, %1; cvt.u32.u64 %0, t; }" : "=r"(a) : "l"(p));
    return a;
}
__device__ __forceinline__ void ldmx4(uint32_t* r, uint32_t addr) {
    asm volatile("ldmatrix.sync.aligned.m8n8.x4.shared.b16 {%0,%1,%2,%3}, [%4];"
                 : "=r"(r[0]), "=r"(r[1]), "=r"(r[2]), "=r"(r[3]) : "r"(addr));
}
__device__ __forceinline__ void mma16816(float* c, const uint32_t* a, const uint32_t* b) {
    asm volatile("mma.sync.aligned.m16n8k16.row.col.f32.bf16.bf16.f32 "
                 "{%0,%1,%2,%3}, {%4,%5,%6,%7}, {%8,%9}, {%0,%1,%2,%3};"
                 : "+f"(c[0]), "+f"(c[1]), "+f"(c[2]), "+f"(c[3])
                 : "r"(a[0]), "r"(a[1]), "r"(a[2]), "r"(a[3]), "r"(b[0]), "r"(b[1]));
}
__device__ __forceinline__ void cp16(uint32_t dst, const void* src) {
    asm volatile("cp.async.cg.shared.global [%0], [%1], 16;" :: "r"(dst), "l"(src));
}
#define CPCOMMIT() asm volatile("cp.async.commit_group;" ::: "memory")
#define CPWAIT0()  asm volatile("cp.async.wait_group 0;" ::: "memory")

// ---------------- 0) split-bf16 conversion (X, W, R^T) ----------------
__global__ void kconv(const float* __restrict__ x,
                      const float* __restrict__ wq, const float* __restrict__ wk,
                      const float* __restrict__ wv, const float* __restrict__ rel)
{
    int i = blockIdx.x * 256 + threadIdx.x;
    float v; __nv_bfloat16* hi; __nv_bfloat16* lo; int o;
    if (i < XN) {
        v = x[i]; hi = g_Xhi; lo = g_Xlo; o = i;
    } else if (i < XN + 3 * WN) {
        int j = i - XN;
        int w = j / WN; o = j - w * WN;
        v = (w == 0 ? wq : (w == 1 ? wk : wv))[o];
        hi = g_Whi + w * WN; lo = g_Wlo + w * WN;
    } else {
        int j = i - XN - 3 * WN;          // 0..NREL*4096
        int r = j >> 12;
        int rem = j & 4095;
        int kk = rem >> 6;
        int nn = rem & 63;
        v = rel[j];
        o = (r << 12) + nn * 64 + kk;     // transposed store
        hi = g_Rhi; lo = g_Rlo;
    }
    __nv_bfloat16 h = __float2bfloat16(v);
    hi[o] = h;
    lo[o] = __float2bfloat16(v - __bfloat162float(h));
}

// ---------------- 1) QKV projection: mma.sync split-bf16, cp.async 2-stage ----------------
#define ASTR 40                 // padded bf16 row stride
#define QBUF (128 * ASTR * 2)   // bytes per operand buffer (10240)
#define QSTG (4 * QBUF)         // bytes per stage (40960)
#define QKV_SMEM (2 * QSTG)     // 81920
__global__ __launch_bounds__(256, 2) void qkv_hmma(
    const float* __restrict__ bq, const float* __restrict__ bk, const float* __restrict__ bv)
{
    extern __shared__ __align__(16) char qsm[];
    const int t = threadIdx.x;
    const int lane = t & 31;
    const int wid = t >> 5;
    const int wr = wid >> 2;        // 0..1  -> 64-row band
    const int wc = wid & 3;         // 0..3  -> 32-col band
    const int n0 = blockIdx.x * 128;
    const int m0 = blockIdx.y * 128;
    const int z  = blockIdx.z;

    const __nv_bfloat16* Wh = g_Whi + z * WN;
    const __nv_bfloat16* Wl = g_Wlo + z * WN;
    const uint32_t sbase = smem_u32(qsm);

    // per-thread load geometry: 2 iters x 4 operands, 16B each
    const int lrow0 = t >> 2;            // iter j: row = lrow0 + 64*j
    const int lf4   = t & 3;

    // preload chunk 0
    {
        const int k0 = 0;
        #pragma unroll
        for (int j = 0; j < 2; j++) {
            int row = lrow0 + 64 * j;
            long goff = (long)row * HIDD + k0 + lf4 * 8;
            uint32_t soff = (uint32_t)(row * ASTR + lf4 * 8) * 2;
            cp16(sbase + 0 * QBUF + soff, g_Xhi + (long)m0 * HIDD + goff);
            cp16(sbase + 1 * QBUF + soff, g_Xlo + (long)m0 * HIDD + goff);
            cp16(sbase + 2 * QBUF + soff, Wh + (long)n0 * HIDD + goff);
            cp16(sbase + 3 * QBUF + soff, Wl + (long)n0 * HIDD + goff);
        }
        CPCOMMIT();
    }

    float acc[4][4][4];
    #pragma unroll
    for (int mi = 0; mi < 4; mi++)
        #pragma unroll
        for (int nj = 0; nj < 4; nj++)
            #pragma unroll
            for (int q = 0; q < 4; q++) acc[mi][nj][q] = 0.f;

    const int g  = lane >> 3;       // octet id 0..3
    const int rr = lane & 7;

    for (int kc = 0; kc < 24; kc++) {
        CPWAIT0();
        __syncthreads();
        if (kc < 23) {
            const int k0 = (kc + 1) * 32;
            const uint32_t stg = sbase + ((kc + 1) & 1) * QSTG;
            #pragma unroll
            for (int j = 0; j < 2; j++) {
                int row = lrow0 + 64 * j;
                long goff = (long)row * HIDD + k0 + lf4 * 8;
                uint32_t soff = (uint32_t)(row * ASTR + lf4 * 8) * 2;
                cp16(stg + 0 * QBUF + soff, g_Xhi + (long)m0 * HIDD + goff);
                cp16(stg + 1 * QBUF + soff, g_Xlo + (long)m0 * HIDD + goff);
                cp16(stg + 2 * QBUF + soff, Wh + (long)n0 * HIDD + goff);
                cp16(stg + 3 * QBUF + soff, Wl + (long)n0 * HIDD + goff);
            }
            CPCOMMIT();
        }

        const uint32_t cs = sbase + (kc & 1) * QSTG;
        const uint32_t sAh_b = cs;
        const uint32_t sAl_b = cs + QBUF;
        const uint32_t sBh_b = cs + 2 * QBUF;
        const uint32_t sBl_b = cs + 3 * QBUF;

        #pragma unroll
        for (int ks = 0; ks < 2; ks++) {
            uint32_t af[4][4], bh[4][2], bl[4][2];
            const int acol = ks * 16 + (g >> 1) * 8;
            #pragma unroll
            for (int mi = 0; mi < 4; mi++) {
                int arow = wr * 64 + mi * 16 + (g & 1) * 8 + rr;
                ldmx4(af[mi], sAh_b + (uint32_t)(arow * ASTR + acol) * 2);
            }
            const int bcol = ks * 16 + (g & 1) * 8;
            #pragma unroll
            for (int np = 0; np < 2; np++) {
                int brow = wc * 32 + np * 16 + (g >> 1) * 8 + rr;
                uint32_t tmp[4];
                ldmx4(tmp, sBh_b + (uint32_t)(brow * ASTR + bcol) * 2);
                bh[2 * np][0] = tmp[0]; bh[2 * np][1] = tmp[1];
                bh[2 * np + 1][0] = tmp[2]; bh[2 * np + 1][1] = tmp[3];
                ldmx4(tmp, sBl_b + (uint32_t)(brow * ASTR + bcol) * 2);
                bl[2 * np][0] = tmp[0]; bl[2 * np][1] = tmp[1];
                bl[2 * np + 1][0] = tmp[2]; bl[2 * np + 1][1] = tmp[3];
            }
            #pragma unroll
            for (int mi = 0; mi < 4; mi++)
                #pragma unroll
                for (int nj = 0; nj < 4; nj++) {
                    mma16816(acc[mi][nj], af[mi], bh[nj]);
                    mma16816(acc[mi][nj], af[mi], bl[nj]);
                }
            #pragma unroll
            for (int mi = 0; mi < 4; mi++) {
                int arow = wr * 64 + mi * 16 + (g & 1) * 8 + rr;
                ldmx4(af[mi], sAl_b + (uint32_t)(arow * ASTR + acol) * 2);
            }
            #pragma unroll
            for (int mi = 0; mi < 4; mi++)
                #pragma unroll
                for (int nj = 0; nj < 4; nj++)
                    mma16816(acc[mi][nj], af[mi], bh[nj]);
        }
    }

    // epilogue
    const float* bias = (z == 0) ? bq : (z == 1) ? bk : bv;
    #pragma unroll
    for (int mi = 0; mi < 4; mi++) {
        int row = m0 + wr * 64 + mi * 16 + (lane >> 2);
        #pragma unroll
        for (int nj = 0; nj < 4; nj++) {
            int col = n0 + wc * 32 + nj * 8 + (lane & 3) * 2;
            float b0 = bias[col], b1 = bias[col + 1];
            float v00 = acc[mi][nj][0] + b0, v01 = acc[mi][nj][1] + b1;
            float v10 = acc[mi][nj][2] + b0, v11 = acc[mi][nj][3] + b1;
            if (z == 0) {
                __nv_bfloat16 h00 = __float2bfloat16(v00), h01 = __float2bfloat16(v01);
                __nv_bfloat16 h10 = __float2bfloat16(v10), h11 = __float2bfloat16(v11);
                __nv_bfloat162 hi0; hi0.x = h00; hi0.y = h01;
                __nv_bfloat162 hi1; hi1.x = h10; hi1.y = h11;
                __nv_bfloat162 lo0; lo0.x = __float2bfloat16(v00 - __bfloat162float(h00));
                                    lo0.y = __float2bfloat16(v01 - __bfloat162float(h01));
                __nv_bfloat162 lo1; lo1.x = __float2bfloat16(v10 - __bfloat162float(h10));
                                    lo1.y = __float2bfloat16(v11 - __bfloat162float(h11));
                *(__nv_bfloat162*)(g_Qhi + (long)row * HIDD + col) = hi0;
                *(__nv_bfloat162*)(g_Qhi + (long)(row + 8) * HIDD + col) = hi1;
                *(__nv_bfloat162*)(g_Qlo + (long)row * HIDD + col) = lo0;
                *(__nv_bfloat162*)(g_Qlo + (long)(row + 8) * HIDD + col) = lo1;
            } else {
                float* outp = (z == 1) ? g_K : g_V;
                *(float2*)(outp + (long)row * HIDD + col) = make_float2(v00, v01);
                *(float2*)(outp + (long)(row + 8) * HIDD + col) = make_float2(v10, v11);
            }
        }
    }
}

// ---------------- 2) deterministic counting sorts ----------------
__global__ void khist(const int* __restrict__ ei)
{
    __shared__ int cnt[NSEG];
    const int c = blockIdx.x;
    for (int i = threadIdx.x; i < NSEG; i += 256) cnt[i] = 0;
    __syncthreads();
    const int e = c * CHUNK + threadIdx.x;
    const int s = ei[e] * Nn + ei[Ee + e];
    atomicAdd(&cnt[s], 1);
    __syncthreads();
    for (int i = threadIdx.x; i < NSEG; i += 256) g_hist[c * NSEG + i] = (unsigned short)cnt[i];
}

// warp-per-segment: per-chunk exclusive prefix (into g_base) + totals (g_cnt)
__global__ void kbasewarp()
{
    const int t = threadIdx.x;
    const int s = blockIdx.x * 8 + (t >> 5);
    const int lane = t & 31;
    int v[8]; int sum = 0;
    #pragma unroll
    for (int i = 0; i < 8; i++) {
        v[i] = g_hist[(lane * 8 + i) * NSEG + s];
        sum += v[i];
    }
    int ex = sum;
    #pragma unroll
    for (int off = 1; off < 32; off <<= 1) {
        int n = __shfl_up_sync(0xffffffffu, ex, off);
        if (lane >= off) ex += n;
    }
    int run = ex - sum;   // exclusive base for this lane's 8 chunks
    #pragma unroll
    for (int i = 0; i < 8; i++) {
        g_base[(lane * 8 + i) * NSEG + s] = (unsigned short)run;
        run += v[i];
    }
    if (lane == 31) g_cnt[s] = run;
}

// hierarchical scan of g_cnt (2048) -> g_start
__global__ void kscan()
{
    __shared__ int wsum[32];
    const int t = threadIdx.x;   // 1024
    const int lane = t & 31, w = t >> 5;
    int a = g_cnt[2 * t], b = g_cnt[2 * t + 1];
    int s = a + b;
    int x = s;
    #pragma unroll
    for (int off = 1; off < 32; off <<= 1) {
        int n = __shfl_up_sync(0xffffffffu, x, off);
        if (lane >= off) x += n;
    }
    if (lane == 31) wsum[w] = x;
    __syncthreads();
    if (w == 0) {
        int y = wsum[lane];
        #pragma unroll
        for (int off = 1; off < 32; off <<= 1) {
            int n = __shfl_up_sync(0xffffffffu, y, off);
            if (lane >= off) y += n;
        }
        wsum[lane] = y;
    }
    __syncthreads();
    int base = (w ? wsum[w - 1] : 0) + x - s;  // exclusive prefix for this pair
    g_start[2 * t + 1] = base + a;
    g_start[2 * t + 2] = base + a + b;
    if (t == 0) g_start[0] = 0;
}

__global__ void kscatter(const int* __restrict__ ei)
{
    __shared__ int segs[CHUNK];
    const int c = blockIdx.x;
    const int t = threadIdx.x;
    const int e = c * CHUNK + t;
    const int s = ei[e] * Nn + ei[Ee + e];
    segs[t] = s;
    __syncthreads();
    int rank = 0;
    for (int i = 0; i < t; i++) rank += (segs[i] == s);
    g_sorted[g_start[s] + (int)g_base[c * NSEG + s] + rank] = e;
}

// relation sort (64 bins)
__global__ void rhist(const int* __restrict__ ei)
{
    __shared__ int cnt[NREL];
    const int c = blockIdx.x;
    const int t = threadIdx.x;
    if (t < NREL) cnt[t] = 0;
    __syncthreads();
    atomicAdd(&cnt[ei[3 * Ee + c * CHUNK + t]], 1);
    __syncthreads();
    if (t < NREL) g_rhist[c * NREL + t] = (unsigned short)cnt[t];
}

__global__ void rprep()
{
    __shared__ int tot[NREL];
    const int t = threadIdx.x;   // 64 threads
    if (t < NREL) {
        int run = 0;
        for (int c = 0; c < NCHUNK; c++) {
            g_rbase[c * NREL + t] = (unsigned short)run;
            run += g_rhist[c * NREL + t];
        }
        tot[t] = run;
    }
    __syncthreads();
    if (t == 0) {
        int s = 0;
        for (int i = 0; i < NREL; i++) { g_rstart[i] = s; s += tot[i]; }
        g_rstart[NREL] = s;
    }
}

__global__ void rscatter(const int* __restrict__ ei)
{
    __shared__ int rels[CHUNK];
    const int c = blockIdx.x;
    const int t = threadIdx.x;
    const int e = c * CHUNK + t;
    const int r = ei[3 * Ee + e];
    rels[t] = r;
    __syncthreads();
    int rank = 0;
    for (int i = 0; i < t; i++) rank += (rels[i] == r);
    g_rsorted[g_rstart[r] + (int)g_rbase[c * NREL + r] + rank] = e;
}

// ---------------- 3) relation-batched logits on tensor cores ----------------
#define RSTR 72   // bf16 elem stride (144B rows -> conflict-free ldmatrix)
#define KSTR 68   // f32 elem stride (16B-aligned, staggered banks)
#define EDGE_SMEM (18432 + 18432 + 34816 + 9216 + 9216 + 192)
__global__ __launch_bounds__(256) void kedge2(const int* __restrict__ ei)
{
    extern __shared__ __align__(16) char sm[];
    __nv_bfloat16* sAh = (__nv_bfloat16*)(sm);
    __nv_bfloat16* sAl = (__nv_bfloat16*)(sm + 18432);
    float*         sK  = (float*)(sm + 36864);
    __nv_bfloat16* sRh = (__nv_bfloat16*)(sm + 71680);
    __nv_bfloat16* sRl = (__nv_bfloat16*)(sm + 80896);
    int* qoff = (int*)(sm + 90112);
    int* koff = qoff + 12;
    int* eidv = koff + 12;

    const int r  = blockIdx.x;
    const int t  = threadIdx.x;
    const int rs = g_rstart[r];
    const int total = (g_rstart[r + 1] - rs) * Hh;   // rows in this relation group
    const int j0 = blockIdx.y * 128;
    if (j0 >= total) return;

    const uint32_t sAh_b = smem_u32(sAh), sAl_b = smem_u32(sAl);
    const uint32_t sRh_b = smem_u32(sRh), sRl_b = smem_u32(sRl);
    const uint32_t sK_b  = smem_u32(sK);

    // R tile loads (independent of edge offsets) — issue first
    {
        const __nv_bfloat16* Rh = g_Rhi + (r << 12);
        const __nv_bfloat16* Rl = g_Rlo + (r << 12);
        #pragma unroll
        for (int i = t; i < 512; i += 256) {
            int n = i >> 3, f = i & 7;
            uint32_t soff = (uint32_t)(n * RSTR + f * 8) * 2;
            cp16(sRh_b + soff, Rh + n * 64 + f * 8);
            cp16(sRl_b + soff, Rl + n * 64 + f * 8);
        }
        CPCOMMIT();
    }

    const int e_first = j0 / Hh;
    const int jlast = min(j0 + 127, total - 1);
    const int nloc = jlast / Hh - e_first + 1;       // <= 12

    if (t < nloc) {
        int e = g_rsorted[rs + e_first + t];
        int b = ei[e], hn = ei[Ee + e], tn = ei[2 * Ee + e];
        qoff[t] = (b * Nn + hn) * HIDD;
        koff[t] = (b * Nn + tn) * HIDD;
        eidv[t] = e;
    }
    __syncthreads();

    // gather A (hi/lo) rows and K rows via cp.async
    #pragma unroll
    for (int i = t; i < 1024; i += 256) {
        int row = i >> 3, f = i & 7;
        int j = j0 + row; if (j > total - 1) j = total - 1;
        int le = j / Hh - e_first;
        int h = j % Hh;
        int off = qoff[le] + h * 64 + f * 8;
        uint32_t soff = (uint32_t)(row * RSTR + f * 8) * 2;
        cp16(sAh_b + soff, g_Qhi + off);
        cp16(sAl_b + soff, g_Qlo + off);
    }
    #pragma unroll
    for (int i = t; i < 2048; i += 256) {
        int row = i >> 4, f = i & 15;
        int j = j0 + row; if (j > total - 1) j = total - 1;
        int le = j / Hh - e_first;
        int h = j % Hh;
        cp16(sK_b + (uint32_t)(row * KSTR + f * 4) * 4, g_K + koff[le] + h * 64 + f * 4);
    }
    CPCOMMIT();
    CPWAIT0();
    __syncthreads();

    const int lane = t & 31;
    const int wm = t >> 5;          // warp -> rows wm*16..+15
    const int g = lane >> 3, rr = lane & 7;

    float acc[8][4];
    #pragma unroll
    for (int nt = 0; nt < 8; nt++)
        #pragma unroll
        for (int q = 0; q < 4; q++) acc[nt][q] = 0.f;

    #pragma unroll
    for (int ks = 0; ks < 4; ks++) {
        uint32_t bh[8][2], bl[8][2], af[4];
        const int bcol = ks * 16 + (g & 1) * 8;
        #pragma unroll
        for (int np = 0; np < 4; np++) {
            int brow = np * 16 + (g >> 1) * 8 + rr;
            uint32_t tmp[4];
            ldmx4(tmp, sRh_b + (uint32_t)(brow * RSTR + bcol) * 2);
            bh[2 * np][0] = tmp[0]; bh[2 * np][1] = tmp[1];
            bh[2 * np + 1][0] = tmp[2]; bh[2 * np + 1][1] = tmp[3];
            ldmx4(tmp, sRl_b + (uint32_t)(brow * RSTR + bcol) * 2);
            bl[2 * np][0] = tmp[0]; bl[2 * np][1] = tmp[1];
            bl[2 * np + 1][0] = tmp[2]; bl[2 * np + 1][1] = tmp[3];
        }
        const int acol = ks * 16 + (g >> 1) * 8;
        const int arow = wm * 16 + (g & 1) * 8 + rr;
        ldmx4(af, sAh_b + (uint32_t)(arow * RSTR + acol) * 2);
        #pragma unroll
        for (int nt = 0; nt < 8; nt++) {
            mma16816(acc[nt], af, bh[nt]);
            mma16816(acc[nt], af, bl[nt]);
        }
        ldmx4(af, sAl_b + (uint32_t)(arow * RSTR + acol) * 2);
        #pragma unroll
        for (int nt = 0; nt < 8; nt++)
            mma16816(acc[nt], af, bh[nt]);
    }

    // epilogue: dot Qp rows with K rows (fp32)
    const int rlo = wm * 16 + (lane >> 2);
    const int rhi = rlo + 8;
    float slo = 0.f, shi = 0.f;
    #pragma unroll
    for (int nt = 0; nt < 8; nt++) {
        int col = nt * 8 + (lane & 3) * 2;
        slo += acc[nt][0] * sK[rlo * KSTR + col] + acc[nt][1] * sK[rlo * KSTR + col + 1];
        shi += acc[nt][2] * sK[rhi * KSTR + col] + acc[nt][3] * sK[rhi * KSTR + col + 1];
    }
    slo += __shfl_xor_sync(0xffffffffu, slo, 1);
    slo += __shfl_xor_sync(0xffffffffu, slo, 2);
    shi += __shfl_xor_sync(0xffffffffu, shi, 1);
    shi += __shfl_xor_sync(0xffffffffu, shi, 2);
    if ((lane & 3) == 0) {
        int j = j0 + rlo;
        if (j < total) {
            int le = j / Hh - e_first;
            g_logits[eidv[le] * Hh + (j % Hh)] = slo * 0.125f;
        }
        j = j0 + rhi;
        if (j < total) {
            int le = j / Hh - e_first;
            g_logits[eidv[le] * Hh + (j % Hh)] = shi * 0.125f;
        }
    }
}

// ---------------- 4) per-segment softmax + V aggregation ----------------
__global__ __launch_bounds__(128) void kagg(const int* __restrict__ ei,
                                            float* __restrict__ out)
{
    __shared__ float    exb[CAP * Hh];   // 24 KB
    __shared__ int      voff[CAP];       // 2 KB
    __shared__ unsigned umax[Hh];
    __shared__ float    mx[Hh], dnm[Hh];

    const int s = blockIdx.x;
    const int t = threadIdx.x;
    const int beg = g_start[s];
    int cnt = g_start[s + 1] - beg;
    if (cnt > CAP) cnt = CAP;
    float* orow = out + s * HIDD;

    if (cnt == 0) {
        #pragma unroll
        for (int j = 0; j < 6; j++) orow[t + 128 * j] = 0.f;
        return;
    }

    if (t < Hh) umax[t] = 0u;
    __syncthreads();

    for (int i = t; i < cnt; i += 128) {
        int e = g_sorted[beg + i];
        voff[i] = (ei[e] * Nn + ei[2 * Ee + e]) * HIDD;
    }
    for (int j = t; j < cnt * Hh; j += 128) {
        int i = j / Hh;
        int h = j - i * Hh;
        int e = g_sorted[beg + i];
        float l = g_logits[e * Hh + h];
        exb[j] = l;
        unsigned bits = __float_as_uint(l);
        unsigned key  = (bits & 0x80000000u) ? ~bits : (bits | 0x80000000u);
        atomicMax(&umax[h], key);   // order-independent -> deterministic
    }
    __syncthreads();

    if (t < Hh) {
        unsigned key  = umax[t];
        unsigned bits = (key & 0x80000000u) ? (key & 0x7fffffffu) : ~key;
        mx[t] = __uint_as_float(bits);
    }
    __syncthreads();

    for (int j = t; j < cnt * Hh; j += 128) {
        int h = j % Hh;
        exb[j] = __expf(exb[j] - mx[h]);
    }
    __syncthreads();

    const int w = t >> 5, lane = t & 31;
    #pragma unroll
    for (int jj = 0; jj < 3; jj++) {
        int h = w * 3 + jj;
        float p = 0.f;
        for (int i = lane; i < cnt; i += 32) p += exb[i * Hh + h];
        #pragma unroll
        for (int off = 16; off; off >>= 1) p += __shfl_xor_sync(0xffffffffu, p, off);
        if (lane == 0) dnm[h] = p;
    }
    __syncthreads();

    float rd[6], accr[6];
    int hcol[6];
    #pragma unroll
    for (int j = 0; j < 6; j++) {
        int c = t + 128 * j;
        hcol[j] = c >> 6;
        rd[j] = 1.f / dnm[hcol[j]];
        accr[j] = 0.f;
    }
    for (int i = 0; i < cnt; i++) {
        const float* vrow = g_V + voff[i];
        const float* exr  = &exb[i * Hh];
        #pragma unroll
        for (int j = 0; j < 6; j++) {
            float p = exr[hcol[j]] * rd[j];
            accr[j] += p * vrow[t + 128 * j];
        }
    }
    #pragma unroll
    for (int j = 0; j < 6; j++) orow[t + 128 * j] = accr[j];
}

// ---------------- launch ----------------
extern "C" void kernel_launch(void* const* d_in, const int* in_sizes, int n_in,
                              void* d_out, int out_size)
{
    const float* node_states = (const float*)d_in[0];
    const int*   edge_idx    = (const int*)  d_in[1];
    // d_in[2] = node_type_ids (unused)
    const float* Wq = (const float*)d_in[3];
    const float* bq = (const float*)d_in[4];
    const float* Wk = (const float*)d_in[5];
    const float* bk = (const float*)d_in[6];
    const float* Wv = (const float*)d_in[7];
    const float* bv = (const float*)d_in[8];
    const float* rel = (const float*)d_in[9];
    float* out = (float*)d_out;

    static bool attr_done = false;
    if (!attr_done) {
        cudaFuncSetAttribute(kedge2, cudaFuncAttributeMaxDynamicSharedMemorySize, EDGE_SMEM);
        cudaFuncSetAttribute(qkv_hmma, cudaFuncAttributeMaxDynamicSharedMemorySize, QKV_SMEM);
        attr_done = true;
    }

    // split-bf16 conversion of X, W, R^T
    kconv<<<(XN + 3 * WN + NREL * 4096) / 256, 256>>>(node_states, Wq, Wk, Wv, rel);

    // QKV projections on tensor cores (cp.async pipelined)
    qkv_hmma<<<dim3(6, 16, 3), 256, QKV_SMEM>>>(bq, bk, bv);

    // deterministic counting sort by segment
    khist<<<NCHUNK, 256>>>(edge_idx);
    kbasewarp<<<NSEG / 8, 256>>>();
    kscan<<<1, 1024>>>();
    kscatter<<<NCHUNK, CHUNK>>>(edge_idx);

    // deterministic counting sort by relation
    rhist<<<NCHUNK, 256>>>(edge_idx);
    rprep<<<1, 64>>>();
    rscatter<<<NCHUNK, CHUNK>>>(edge_idx);

    // relation-batched logits on tensor cores
    kedge2<<<dim3(NREL, 120), 256, EDGE_SMEM>>>(edge_idx);

    // per-segment softmax + aggregation
    kagg<<<NSEG, 128>>>(edge_idx, out);
}